// round 8
// baseline (speedup 1.0000x reference)
#include <cuda_runtime.h>
#include <cuda_bf16.h>
#include <cstdint>

#define GENE   2000
#define TE     128
#define HID    2048
#define KIN    2128      // GENE + TE (time embedding lives in x tail)
#define NSTEP  256
#define GRID   128
#define BLOCK  512
#define NCOL   16        // output columns per CTA
#define DT     (1.0f/255.0f)
#define CHUNK  512
#define NBUF   5
#define LOOKAHEAD 4                         // chunks in flight; wait_group 3
#define BUF_BYTES (CHUNK*NCOL*2)            // 16 KB (bf16)
#define XS_FLOATS 2176
#define SMEM_BYTES (XS_FLOATS*4 + NBUF*BUF_BYTES)
#define LEAVES 16
#define PER_LEAF (GRID/LEAVES)              // 8

// Permuted bf16 weights: per-CTA slice contiguous.
#define OFF0   0L
#define OFF1   (OFF0 + 128L*KIN*NCOL)
#define OFF2   (OFF1 + 128L*HID*NCOL)
#define OFF3   (OFF2 + 128L*HID*NCOL)
#define OFF4   (OFF3 + 128L*HID*NCOL)
#define OFFO   (OFF4 + 128L*HID*NCOL)
#define TOTALF (OFFO + 125L*HID*NCOL)       // ~25.2M bf16 = ~48 MB

// Persistent scratch (device globals: allocation is forbidden)
__device__ __nv_bfloat16 g_wrep[TOTALF];
__device__ float    g_x[2][2176];      // x ping-pong: [0,2000)=x, [2000,2128)=te(t)
__device__ float    g_h0[HID];
__device__ float    g_h1[HID];
__device__ float    g_te[NSTEP][TE];
// Tree barrier: each counter on its OWN 128-B LTS line (load-bearing: adjacent
// counters share a line and the RMWs serialize exactly like a flat counter).
__device__ unsigned g_leafpad[LEAVES][32];
__device__ unsigned g_rootpad[32];

// ---------------------------------------------------------------------------
// Grid barrier: padded two-level tree. 8 same-line RMWs per leaf (parallel
// across 16 distinct lines) + 16 root RMWs; pollers touch the root line only.
// ---------------------------------------------------------------------------
__device__ __forceinline__ void grid_barrier(unsigned& nbar) {
    __syncthreads();
    ++nbar;
    if (threadIdx.x == 0) {
        __threadfence();
        unsigned old;
        asm volatile("atom.acq_rel.gpu.global.add.u32 %0, [%1], 1;"
                     : "=r"(old)
                     : "l"(&g_leafpad[blockIdx.x & (LEAVES-1)][0]) : "memory");
        if (old == nbar * PER_LEAF - 1)
            asm volatile("red.release.gpu.global.add.u32 [%0], 1;"
                         :: "l"(&g_rootpad[0]) : "memory");
        const unsigned target = nbar * LEAVES;
        unsigned cur;
        do {
            asm volatile("ld.acquire.gpu.global.u32 %0, [%1];"
                         : "=r"(cur) : "l"(&g_rootpad[0]) : "memory");
        } while (cur < target);
    }
    __syncthreads();
}

// ---------------------------------------------------------------------------
// cp.async helpers
// ---------------------------------------------------------------------------
__device__ __forceinline__ void cp16(char* dst, const char* src) {
    unsigned a = (unsigned)__cvta_generic_to_shared(dst);
    asm volatile("cp.async.cg.shared.global [%0], [%1], 16;" :: "r"(a), "l"(src));
}

// One CHUNK-row slab (bf16, contiguous) -> smem buf. One commit, all threads.
__device__ __forceinline__ void prefetch_chunk(const char* __restrict__ slice,
        int K, int base, char* __restrict__ buf, int tid, bool active) {
    if (active) {
        const int lim = K * 2;            // 16B segments in whole slice
        const int s0  = base * 2;         // first 16B segment of this chunk
        #pragma unroll
        for (int i = 0; i < (CHUNK*2)/BLOCK; ++i) {   // 2 segs/thread
            const int s = tid + i*BLOCK;
            if (s0 + s < lim)
                cp16(buf + s*16, slice + (long)(s0 + s)*16);
        }
    }
    asm volatile("cp.async.commit_group;");
}

// ---------------------------------------------------------------------------
// Layer. Invariant: on entry, this layer's chunks 0..LOOKAHEAD-1 are in
// flight. During its nc iterations it issues its remaining chunks, then
// chunks 0..LOOKAHEAD-1 of the NEXT layer. One wait_group + one
// __syncthreads per chunk. Result valid for tid<4 (float4 at cols j0+tid*4).
// ---------------------------------------------------------------------------
__device__ __forceinline__ float4 layer_core(
    const char* __restrict__ slice,  int K,  bool act,
    const char* __restrict__ slicen, int Kn, bool actn,
    const float* __restrict__ in,
    float* __restrict__ xs, char* __restrict__ bufs,
    int& is, int& rs, float4 (*red)[4],
    int tid, unsigned& nbar)
{
    grid_barrier(nbar);

    // Stage input vector (fresh data from other SMs -> L2 path).
    const int K4 = K >> 2;
    for (int i = tid; i < K4; i += BLOCK)
        reinterpret_cast<float4*>(xs)[i] =
            __ldcg(reinterpret_cast<const float4*>(in) + i);

    const int kw = tid >> 2;
    const int jv = tid & 3;
    float4 acc = make_float4(0.f, 0.f, 0.f, 0.f);

    const int nc = (K + CHUNK - 1) / CHUNK;
    for (int c = 0; c < nc; ++c) {
        asm volatile("cp.async.wait_group 3;");   // chunk c landed
        __syncthreads();                          // ..and chunk c-1 reads done

        // Refill the buffer freed by the sync just passed.
        if (c < nc - LOOKAHEAD)
            prefetch_chunk(slice,  K,  (c + LOOKAHEAD)*CHUNK,
                           bufs + is*BUF_BYTES, tid, act);
        else
            prefetch_chunk(slicen, Kn, (c - (nc - LOOKAHEAD))*CHUNK,
                           bufs + is*BUF_BYTES, tid, actn);
        if (++is == NBUF) is = 0;

        if (act) {
            const char* __restrict__ buf = bufs + rs*BUF_BYTES;
            const int base = c * CHUNK;
            const int rows = min(CHUNK, K - base);
            #pragma unroll
            for (int i = 0; i < CHUNK/(BLOCK/4); ++i) {
                const int r = kw + i*(BLOCK/4);
                if (r < rows) {
                    const float xv = xs[base + r];
                    const uint2 wv = *reinterpret_cast<const uint2*>(buf + r*32 + jv*8);
                    const float2 f0 = __bfloat1622float2(
                        *reinterpret_cast<const __nv_bfloat162*>(&wv.x));
                    const float2 f1 = __bfloat1622float2(
                        *reinterpret_cast<const __nv_bfloat162*>(&wv.y));
                    acc.x = fmaf(xv, f0.x, acc.x);
                    acc.y = fmaf(xv, f0.y, acc.y);
                    acc.z = fmaf(xv, f1.x, acc.z);
                    acc.w = fmaf(xv, f1.y, acc.w);
                }
            }
        }
        if (++rs == NBUF) rs = 0;
    }

    // Warp reduce over the 8 kw groups inside each warp (lane bits 2..4)
    #pragma unroll
    for (int m = 4; m <= 16; m <<= 1) {
        acc.x += __shfl_xor_sync(0xffffffffu, acc.x, m);
        acc.y += __shfl_xor_sync(0xffffffffu, acc.y, m);
        acc.z += __shfl_xor_sync(0xffffffffu, acc.z, m);
        acc.w += __shfl_xor_sync(0xffffffffu, acc.w, m);
    }
    const int warp = tid >> 5;
    const int lane = tid & 31;
    if (lane < 4) red[warp][lane] = acc;
    __syncthreads();

    float4 r = make_float4(0.f, 0.f, 0.f, 0.f);
    if (tid < 32) {                    // warp 0 reduces 16 warp-partials
        const int wi = tid >> 2;
        const int j  = tid & 3;
        const float4 a = red[wi][j];
        const float4 b = red[wi + 8][j];
        r.x = a.x + b.x; r.y = a.y + b.y; r.z = a.z + b.z; r.w = a.w + b.w;
        #pragma unroll
        for (int m = 4; m <= 16; m <<= 1) {
            r.x += __shfl_xor_sync(0xffffffffu, r.x, m);
            r.y += __shfl_xor_sync(0xffffffffu, r.y, m);
            r.z += __shfl_xor_sync(0xffffffffu, r.z, m);
            r.w += __shfl_xor_sync(0xffffffffu, r.w, m);
        }
    }
    return r;   // valid for tid < 4
}

__device__ __forceinline__ void store_hidden(float4 r,
        const float* __restrict__ bias, float* __restrict__ out,
        int j0, int tid)
{
    if (tid < 4) {
        const float4 b = __ldg(reinterpret_cast<const float4*>(bias + j0) + tid);
        r.x = fmaxf(r.x + b.x, 0.f);
        r.y = fmaxf(r.y + b.y, 0.f);
        r.z = fmaxf(r.z + b.z, 0.f);
        r.w = fmaxf(r.w + b.w, 0.f);
        reinterpret_cast<float4*>(out + j0)[tid] = r;
    }
}

// ---------------------------------------------------------------------------
// Weight reorg: permute + convert fp32 -> bf16, per-CTA-slice contiguous.
// ---------------------------------------------------------------------------
__global__ void reorg_kernel(
    const float* __restrict__ w0, const float* __restrict__ w1,
    const float* __restrict__ w2, const float* __restrict__ w3,
    const float* __restrict__ w4, const float* __restrict__ wout)
{
    const int b = blockIdx.x;   // slice
    const int l = blockIdx.y;   // layer
    const float* W; int K, O; long off;
    switch (l) {
        case 0: W = w0;   K = KIN; O = HID;  off = OFF0; break;
        case 1: W = w1;   K = HID; O = HID;  off = OFF1; break;
        case 2: W = w2;   K = HID; O = HID;  off = OFF2; break;
        case 3: W = w3;   K = HID; O = HID;  off = OFF3; break;
        case 4: W = w4;   K = HID; O = HID;  off = OFF4; break;
        default:W = wout; K = HID; O = GENE; off = OFFO; break;
    }
    const int j0 = b * NCOL;
    if (j0 >= O) return;
    __nv_bfloat16* dst = g_wrep + off + (long)b * K * NCOL;
    const int n4 = K * (NCOL/4);
    for (int e = threadIdx.x; e < n4; e += blockDim.x) {
        const int r  = e >> 2;
        const int c4 = (e & 3) * 4;
        const float4 w = *reinterpret_cast<const float4*>(W + (long)r * O + j0 + c4);
        uint2 p;
        __nv_bfloat162 p0 = __float22bfloat162_rn(make_float2(w.x, w.y));
        __nv_bfloat162 p1 = __float22bfloat162_rn(make_float2(w.z, w.w));
        p.x = *reinterpret_cast<unsigned*>(&p0);
        p.y = *reinterpret_cast<unsigned*>(&p1);
        *reinterpret_cast<uint2*>(dst + (long)e * 4) = p;
    }
}

// ---------------------------------------------------------------------------
// Init: reset barrier counters, seed x0 (+te(1) tail) + row 0, precompute te.
// ---------------------------------------------------------------------------
__global__ void init_kernel(
    const float* __restrict__ start,
    const float* __restrict__ te_w1, const float* __restrict__ te_b1,
    const float* __restrict__ te_w2, const float* __restrict__ te_b2,
    float* __restrict__ out)
{
    const int b   = blockIdx.x;     // 0..255
    const int tid = threadIdx.x;    // 128 threads
    if (b == 0) {
        if (tid == 0) g_rootpad[0] = 0u;
        if (tid < LEAVES) g_leafpad[tid][0] = 0u;
        for (int k = tid; k < GENE; k += TE) {
            const float v = start[k];
            g_x[0][k] = v;
            out[k]    = v;          // trajectory row 0
        }
    } else {
        const float t = (float)b * DT;
        __shared__ float h[TE];
        h[tid] = fmaxf(fmaf(t, te_w1[tid], te_b1[tid]), 0.f);
        __syncthreads();
        float acc = te_b2[tid];
        #pragma unroll 8
        for (int k = 0; k < TE; ++k)
            acc = fmaf(h[k], te_w2[k * TE + tid], acc);
        g_te[b][tid] = acc;
        if (b == 1) g_x[0][GENE + tid] = acc;   // te(1) tail for step 1
    }
}

// ---------------------------------------------------------------------------
// Persistent kernel: 255 Euler steps, 6 tree barriers/step, depth-5 cp.async
// streaming of contiguous bf16 weight slices, 4-chunk cross-layer lookahead.
// ---------------------------------------------------------------------------
__global__ void __launch_bounds__(BLOCK, 1) bridge_kernel(
    const float* __restrict__ b0, const float* __restrict__ b1,
    const float* __restrict__ b2, const float* __restrict__ b3,
    const float* __restrict__ b4, const float* __restrict__ bout,
    float* __restrict__ out)
{
    extern __shared__ float smem[];
    float* xs   = smem;                                 // 2176 floats
    char*  bufs = reinterpret_cast<char*>(smem + XS_FLOATS);
    __shared__ float4 red[16][4];

    const int tid = threadIdx.x;
    const int b   = blockIdx.x;
    const int j0  = b * NCOL;
    const bool actO = (j0 < GENE);      // active in the output layer

    const char* s0 = reinterpret_cast<const char*>(g_wrep + OFF0 + (long)b * KIN * NCOL);
    const char* s1 = reinterpret_cast<const char*>(g_wrep + OFF1 + (long)b * HID * NCOL);
    const char* s2 = reinterpret_cast<const char*>(g_wrep + OFF2 + (long)b * HID * NCOL);
    const char* s3 = reinterpret_cast<const char*>(g_wrep + OFF3 + (long)b * HID * NCOL);
    const char* s4 = reinterpret_cast<const char*>(g_wrep + OFF4 + (long)b * HID * NCOL);
    const char* so = reinterpret_cast<const char*>(g_wrep + OFFO + (long)b * HID * NCOL);

    unsigned nbar = 0;
    int is = 0, rs = 0;

    // Prologue: chunks 0..3 of step-1 layer0
    #pragma unroll
    for (int c = 0; c < LOOKAHEAD; ++c)
        prefetch_chunk(s0, KIN, c*CHUNK, bufs + c*BUF_BYTES, tid, true);
    is = LOOKAHEAD;

    for (int t = 1; t < NSTEP; ++t) {
        const float* xprev = g_x[(t - 1) & 1];
        float*       xcur  = g_x[t & 1];
        float4 r;

        r = layer_core(s0, KIN, true,  s1, HID, true,  xprev,
                       xs, bufs, is, rs, red, tid, nbar);
        store_hidden(r, b0, g_h0, j0, tid);

        r = layer_core(s1, HID, true,  s2, HID, true,  g_h0,
                       xs, bufs, is, rs, red, tid, nbar);
        store_hidden(r, b1, g_h1, j0, tid);

        r = layer_core(s2, HID, true,  s3, HID, true,  g_h1,
                       xs, bufs, is, rs, red, tid, nbar);
        store_hidden(r, b2, g_h0, j0, tid);

        r = layer_core(s3, HID, true,  s4, HID, true,  g_h0,
                       xs, bufs, is, rs, red, tid, nbar);
        store_hidden(r, b3, g_h1, j0, tid);

        r = layer_core(s4, HID, true,  so, HID, actO,  g_h1,
                       xs, bufs, is, rs, red, tid, nbar);
        store_hidden(r, b4, g_h0, j0, tid);

        // Final layer + Euler update + trajectory store
        r = layer_core(so, HID, actO,  s0, KIN, true,  g_h0,
                       xs, bufs, is, rs, red, tid, nbar);
        if (tid < 4 && actO) {
            const float4 bb = __ldg(reinterpret_cast<const float4*>(bout + j0) + tid);
            const float4 xp = __ldcg(reinterpret_cast<const float4*>(xprev + j0) + tid);
            float4 xn;
            xn.x = fmaf(r.x + bb.x, DT, xp.x);
            xn.y = fmaf(r.y + bb.y, DT, xp.y);
            xn.z = fmaf(r.z + bb.z, DT, xp.z);
            xn.w = fmaf(r.w + bb.w, DT, xp.w);
            reinterpret_cast<float4*>(xcur + j0)[tid] = xn;
            __stcs(reinterpret_cast<float4*>(out + (size_t)t * GENE + j0) + tid, xn);
        }
        // tail CTA installs te(t+1) into xcur tail for next step's layer0
        if (b == GRID - 1 && t + 1 < NSTEP && tid < TE)
            xcur[GENE + tid] = g_te[t + 1][tid];
    }
}

extern "C" void kernel_launch(void* const* d_in, const int* in_sizes, int n_in,
                              void* d_out, int out_size)
{
    (void)in_sizes; (void)n_in; (void)out_size;
    const float* start  = (const float*)d_in[0];
    // d_in[1] = end_state (unused)
    const float* te_w1  = (const float*)d_in[2];
    const float* te_b1  = (const float*)d_in[3];
    const float* te_w2  = (const float*)d_in[4];
    const float* te_b2  = (const float*)d_in[5];
    const float* w0     = (const float*)d_in[6];
    const float* b0     = (const float*)d_in[7];
    const float* w1     = (const float*)d_in[8];
    const float* b1     = (const float*)d_in[9];
    const float* w2     = (const float*)d_in[10];
    const float* b2     = (const float*)d_in[11];
    const float* w3     = (const float*)d_in[12];
    const float* b3     = (const float*)d_in[13];
    const float* w4     = (const float*)d_in[14];
    const float* b4     = (const float*)d_in[15];
    const float* wout   = (const float*)d_in[16];
    const float* bout   = (const float*)d_in[17];
    float* out = (float*)d_out;

    cudaFuncSetAttribute(bridge_kernel,
                         cudaFuncAttributeMaxDynamicSharedMemorySize, SMEM_BYTES);

    dim3 rg(GRID, 6);
    reorg_kernel<<<rg, 256>>>(w0, w1, w2, w3, w4, wout);
    init_kernel<<<NSTEP, TE>>>(start, te_w1, te_b1, te_w2, te_b2, out);
    bridge_kernel<<<GRID, BLOCK, SMEM_BYTES>>>(b0, b1, b2, b3, b4, bout, out);
}

// round 9
// speedup vs baseline: 1.4842x; 1.4842x over previous
#include <cuda_runtime.h>
#include <cuda_bf16.h>
#include <cstdint>

#define GENE   2000
#define TE     128
#define HID    2048
#define KIN    2128      // GENE + TE (time embedding lives in x tail)
#define NSTEP  256
#define GRID   128
#define BLOCK  512
#define NCOL   16        // output columns per CTA
#define DT     (1.0f/255.0f)
#define CHUNK  1024                         // weight rows per cp.async chunk
#define NBUF   3
#define LOOKAHEAD 2                         // chunks in flight; wait_group 1
#define BUF_BYTES (CHUNK*NCOL*2)            // 32 KB (bf16)
#define XS_FLOATS 2176
#define SMEM_BYTES (XS_FLOATS*4 + NBUF*BUF_BYTES)

// Permuted bf16 weights: per-CTA slice contiguous.
#define OFF0   0L
#define OFF1   (OFF0 + 128L*KIN*NCOL)
#define OFF2   (OFF1 + 128L*HID*NCOL)
#define OFF3   (OFF2 + 128L*HID*NCOL)
#define OFF4   (OFF3 + 128L*HID*NCOL)
#define OFFO   (OFF4 + 128L*HID*NCOL)
#define TOTALF (OFFO + 125L*HID*NCOL)       // ~25.2M bf16 = ~48 MB

// Persistent scratch (device globals: allocation is forbidden)
__device__ __nv_bfloat16 g_wrep[TOTALF];
__device__ float    g_x[2][2176];      // x ping-pong: [0,2000)=x, [2000,2128)=te(t)
__device__ float    g_h0[HID];
__device__ float    g_h1[HID];
__device__ float    g_te[NSTEP][TE];
__device__ unsigned g_count;           // flat barrier counter (red-based, fast)

// ---------------------------------------------------------------------------
// Grid barrier: FLAT monotonic counter. Arrival = red.release (fire-and-
// forget, 0.854 cyc/lane at the LTS atomic ALU -> ~110 cyc drain for 128
// arrivals). Poll = ld.acquire on the same line. Measured faster than any
// tree variant (blocking acq_rel atomics cost a 318-cyc round trip each).
// ---------------------------------------------------------------------------
__device__ __forceinline__ void grid_barrier(unsigned& nbar) {
    __syncthreads();
    ++nbar;
    if (threadIdx.x == 0) {
        __threadfence();
        asm volatile("red.release.gpu.add.u32 [%0], 1;" :: "l"(&g_count) : "memory");
        const unsigned target = nbar * GRID;
        unsigned cur;
        do {
            asm volatile("ld.acquire.gpu.u32 %0, [%1];" : "=r"(cur) : "l"(&g_count) : "memory");
        } while (cur < target);
    }
    __syncthreads();
}

// ---------------------------------------------------------------------------
// cp.async helpers
// ---------------------------------------------------------------------------
__device__ __forceinline__ void cp16(char* dst, const char* src) {
    unsigned a = (unsigned)__cvta_generic_to_shared(dst);
    asm volatile("cp.async.cg.shared.global [%0], [%1], 16;" :: "r"(a), "l"(src));
}

// One CHUNK-row slab (bf16, contiguous) -> smem buf. One commit, all threads.
__device__ __forceinline__ void prefetch_chunk(const char* __restrict__ slice,
        int K, int base, char* __restrict__ buf, int tid, bool active) {
    if (active) {
        const int lim = K * 2;            // 16B segments in whole slice
        const int s0  = base * 2;
        #pragma unroll
        for (int i = 0; i < (CHUNK*2)/BLOCK; ++i) {   // 4 segs/thread
            const int s = tid + i*BLOCK;
            if (s0 + s < lim)
                cp16(buf + s*16, slice + (long)(s0 + s)*16);
        }
    }
    asm volatile("cp.async.commit_group;");
}

// Stage one 1024-float piece of the input vector into xs.
__device__ __forceinline__ void stage_piece(const float* __restrict__ in,
        float* __restrict__ xs, int p, int K, int tid) {
    const int idx = p*CHUNK + tid*2;
    if (idx < K)
        *reinterpret_cast<float2*>(xs + idx) =
            __ldcg(reinterpret_cast<const float2*>(in + idx));
}

// ---------------------------------------------------------------------------
// Layer. Invariant: on entry this layer's chunks 0..1 are in flight; on exit
// the NEXT layer's chunks 0..1 are in flight. xs piece c+1 staged during
// chunk c (only piece 0's latency is exposed). One wait_group + one
// __syncthreads per chunk. Result valid for tid<4 (float4 at cols j0+tid*4).
// ---------------------------------------------------------------------------
__device__ __forceinline__ float4 layer_core(
    const char* __restrict__ slice,  int K,  bool act,
    const char* __restrict__ slicen, int Kn, bool actn,
    const float* __restrict__ in,
    float* __restrict__ xs, char* __restrict__ bufs,
    int& is, int& rs, float4 (*red)[4],
    int tid, unsigned& nbar)
{
    grid_barrier(nbar);

    stage_piece(in, xs, 0, K, tid);          // piece 0 latency exposed (only)

    const int kw = tid >> 2;
    const int jv = tid & 3;
    float4 acc = make_float4(0.f, 0.f, 0.f, 0.f);

    const int nc = (K + CHUNK - 1) / CHUNK;
    for (int c = 0; c < nc; ++c) {
        asm volatile("cp.async.wait_group 1;");   // chunk c landed (long ago)
        __syncthreads();                          // + piece c visible, c-1 reads done

        // Refill the buffer freed by the sync just passed.
        if (c + LOOKAHEAD < nc)
            prefetch_chunk(slice,  K,  (c + LOOKAHEAD)*CHUNK,
                           bufs + is*BUF_BYTES, tid, act);
        else
            prefetch_chunk(slicen, Kn, (c + LOOKAHEAD - nc)*CHUNK,
                           bufs + is*BUF_BYTES, tid, actn);
        if (++is == NBUF) is = 0;

        stage_piece(in, xs, c + 1, K, tid);       // for next iteration

        if (act) {
            const char* __restrict__ buf = bufs + rs*BUF_BYTES;
            const int base = c * CHUNK;
            const int rows = min(CHUNK, K - base);
            #pragma unroll
            for (int i = 0; i < CHUNK/(BLOCK/4); ++i) {   // 8 iters
                const int r = kw + i*(BLOCK/4);
                if (r < rows) {
                    const float xv = xs[base + r];
                    const uint2 wv = *reinterpret_cast<const uint2*>(buf + r*32 + jv*8);
                    const float2 f0 = __bfloat1622float2(
                        *reinterpret_cast<const __nv_bfloat162*>(&wv.x));
                    const float2 f1 = __bfloat1622float2(
                        *reinterpret_cast<const __nv_bfloat162*>(&wv.y));
                    acc.x = fmaf(xv, f0.x, acc.x);
                    acc.y = fmaf(xv, f0.y, acc.y);
                    acc.z = fmaf(xv, f1.x, acc.z);
                    acc.w = fmaf(xv, f1.y, acc.w);
                }
            }
        }
        if (++rs == NBUF) rs = 0;
    }

    // Warp reduce over the 8 kw groups inside each warp (lane bits 2..4)
    #pragma unroll
    for (int m = 4; m <= 16; m <<= 1) {
        acc.x += __shfl_xor_sync(0xffffffffu, acc.x, m);
        acc.y += __shfl_xor_sync(0xffffffffu, acc.y, m);
        acc.z += __shfl_xor_sync(0xffffffffu, acc.z, m);
        acc.w += __shfl_xor_sync(0xffffffffu, acc.w, m);
    }
    const int warp = tid >> 5;
    const int lane = tid & 31;
    if (lane < 4) red[warp][lane] = acc;
    __syncthreads();

    float4 r = make_float4(0.f, 0.f, 0.f, 0.f);
    if (tid < 32) {                    // warp 0 reduces 16 warp-partials
        const int wi = tid >> 2;
        const int j  = tid & 3;
        const float4 a = red[wi][j];
        const float4 b = red[wi + 8][j];
        r.x = a.x + b.x; r.y = a.y + b.y; r.z = a.z + b.z; r.w = a.w + b.w;
        #pragma unroll
        for (int m = 4; m <= 16; m <<= 1) {
            r.x += __shfl_xor_sync(0xffffffffu, r.x, m);
            r.y += __shfl_xor_sync(0xffffffffu, r.y, m);
            r.z += __shfl_xor_sync(0xffffffffu, r.z, m);
            r.w += __shfl_xor_sync(0xffffffffu, r.w, m);
        }
    }
    return r;   // valid for tid < 4
}

__device__ __forceinline__ void store_hidden(float4 r,
        const float* __restrict__ bias, float* __restrict__ out,
        int j0, int tid)
{
    if (tid < 4) {
        const float4 b = __ldg(reinterpret_cast<const float4*>(bias + j0) + tid);
        r.x = fmaxf(r.x + b.x, 0.f);
        r.y = fmaxf(r.y + b.y, 0.f);
        r.z = fmaxf(r.z + b.z, 0.f);
        r.w = fmaxf(r.w + b.w, 0.f);
        reinterpret_cast<float4*>(out + j0)[tid] = r;
    }
}

// ---------------------------------------------------------------------------
// Weight reorg: permute + convert fp32 -> bf16, per-CTA-slice contiguous.
// ---------------------------------------------------------------------------
__global__ void reorg_kernel(
    const float* __restrict__ w0, const float* __restrict__ w1,
    const float* __restrict__ w2, const float* __restrict__ w3,
    const float* __restrict__ w4, const float* __restrict__ wout)
{
    const int b = blockIdx.x;   // slice
    const int l = blockIdx.y;   // layer
    const float* W; int K, O; long off;
    switch (l) {
        case 0: W = w0;   K = KIN; O = HID;  off = OFF0; break;
        case 1: W = w1;   K = HID; O = HID;  off = OFF1; break;
        case 2: W = w2;   K = HID; O = HID;  off = OFF2; break;
        case 3: W = w3;   K = HID; O = HID;  off = OFF3; break;
        case 4: W = w4;   K = HID; O = HID;  off = OFF4; break;
        default:W = wout; K = HID; O = GENE; off = OFFO; break;
    }
    const int j0 = b * NCOL;
    if (j0 >= O) return;
    __nv_bfloat16* dst = g_wrep + off + (long)b * K * NCOL;
    const int n4 = K * (NCOL/4);
    for (int e = threadIdx.x; e < n4; e += blockDim.x) {
        const int r  = e >> 2;
        const int c4 = (e & 3) * 4;
        const float4 w = *reinterpret_cast<const float4*>(W + (long)r * O + j0 + c4);
        uint2 p;
        __nv_bfloat162 p0 = __float22bfloat162_rn(make_float2(w.x, w.y));
        __nv_bfloat162 p1 = __float22bfloat162_rn(make_float2(w.z, w.w));
        p.x = *reinterpret_cast<unsigned*>(&p0);
        p.y = *reinterpret_cast<unsigned*>(&p1);
        *reinterpret_cast<uint2*>(dst + (long)e * 4) = p;
    }
}

// ---------------------------------------------------------------------------
// Init: reset barrier counter, seed x0 (+te(1) tail) + row 0, precompute te.
// ---------------------------------------------------------------------------
__global__ void init_kernel(
    const float* __restrict__ start,
    const float* __restrict__ te_w1, const float* __restrict__ te_b1,
    const float* __restrict__ te_w2, const float* __restrict__ te_b2,
    float* __restrict__ out)
{
    const int b   = blockIdx.x;     // 0..255
    const int tid = threadIdx.x;    // 128 threads
    if (b == 0) {
        if (tid == 0) g_count = 0u;
        for (int k = tid; k < GENE; k += TE) {
            const float v = start[k];
            g_x[0][k] = v;
            out[k]    = v;          // trajectory row 0
        }
    } else {
        const float t = (float)b * DT;
        __shared__ float h[TE];
        h[tid] = fmaxf(fmaf(t, te_w1[tid], te_b1[tid]), 0.f);
        __syncthreads();
        float acc = te_b2[tid];
        #pragma unroll 8
        for (int k = 0; k < TE; ++k)
            acc = fmaf(h[k], te_w2[k * TE + tid], acc);
        g_te[b][tid] = acc;
        if (b == 1) g_x[0][GENE + tid] = acc;   // te(1) tail for step 1
    }
}

// ---------------------------------------------------------------------------
// Persistent kernel: 255 Euler steps, 6 flat barriers/step, depth-3 cp.async
// (32 KB chunks), full next-layer prefetch across barriers, pieced xs staging.
// ---------------------------------------------------------------------------
__global__ void __launch_bounds__(BLOCK, 1) bridge_kernel(
    const float* __restrict__ b0, const float* __restrict__ b1,
    const float* __restrict__ b2, const float* __restrict__ b3,
    const float* __restrict__ b4, const float* __restrict__ bout,
    float* __restrict__ out)
{
    extern __shared__ float smem[];
    float* xs   = smem;                                 // 2176 floats
    char*  bufs = reinterpret_cast<char*>(smem + XS_FLOATS);
    __shared__ float4 red[16][4];

    const int tid = threadIdx.x;
    const int b   = blockIdx.x;
    const int j0  = b * NCOL;
    const bool actO = (j0 < GENE);

    const char* s0 = reinterpret_cast<const char*>(g_wrep + OFF0 + (long)b * KIN * NCOL);
    const char* s1 = reinterpret_cast<const char*>(g_wrep + OFF1 + (long)b * HID * NCOL);
    const char* s2 = reinterpret_cast<const char*>(g_wrep + OFF2 + (long)b * HID * NCOL);
    const char* s3 = reinterpret_cast<const char*>(g_wrep + OFF3 + (long)b * HID * NCOL);
    const char* s4 = reinterpret_cast<const char*>(g_wrep + OFF4 + (long)b * HID * NCOL);
    const char* so = reinterpret_cast<const char*>(g_wrep + OFFO + (long)b * HID * NCOL);

    unsigned nbar = 0;
    int is = 0, rs = 0;

    // Prologue: chunks 0..1 of step-1 layer0
    prefetch_chunk(s0, KIN, 0*CHUNK, bufs + 0*BUF_BYTES, tid, true);
    prefetch_chunk(s0, KIN, 1*CHUNK, bufs + 1*BUF_BYTES, tid, true);
    is = LOOKAHEAD;

    for (int t = 1; t < NSTEP; ++t) {
        const float* xprev = g_x[(t - 1) & 1];
        float*       xcur  = g_x[t & 1];
        float4 r;

        r = layer_core(s0, KIN, true,  s1, HID, true,  xprev,
                       xs, bufs, is, rs, red, tid, nbar);
        store_hidden(r, b0, g_h0, j0, tid);

        r = layer_core(s1, HID, true,  s2, HID, true,  g_h0,
                       xs, bufs, is, rs, red, tid, nbar);
        store_hidden(r, b1, g_h1, j0, tid);

        r = layer_core(s2, HID, true,  s3, HID, true,  g_h1,
                       xs, bufs, is, rs, red, tid, nbar);
        store_hidden(r, b2, g_h0, j0, tid);

        r = layer_core(s3, HID, true,  s4, HID, true,  g_h0,
                       xs, bufs, is, rs, red, tid, nbar);
        store_hidden(r, b3, g_h1, j0, tid);

        r = layer_core(s4, HID, true,  so, HID, actO,  g_h1,
                       xs, bufs, is, rs, red, tid, nbar);
        store_hidden(r, b4, g_h0, j0, tid);

        // Final layer + Euler update + trajectory store
        r = layer_core(so, HID, actO,  s0, KIN, true,  g_h0,
                       xs, bufs, is, rs, red, tid, nbar);
        if (tid < 4 && actO) {
            const float4 bb = __ldg(reinterpret_cast<const float4*>(bout + j0) + tid);
            const float4 xp = __ldcg(reinterpret_cast<const float4*>(xprev + j0) + tid);
            float4 xn;
            xn.x = fmaf(r.x + bb.x, DT, xp.x);
            xn.y = fmaf(r.y + bb.y, DT, xp.y);
            xn.z = fmaf(r.z + bb.z, DT, xp.z);
            xn.w = fmaf(r.w + bb.w, DT, xp.w);
            reinterpret_cast<float4*>(xcur + j0)[tid] = xn;
            __stcs(reinterpret_cast<float4*>(out + (size_t)t * GENE + j0) + tid, xn);
        }
        // tail CTA installs te(t+1) into xcur tail for next step's layer0
        if (b == GRID - 1 && t + 1 < NSTEP && tid < TE)
            xcur[GENE + tid] = g_te[t + 1][tid];
    }
}

extern "C" void kernel_launch(void* const* d_in, const int* in_sizes, int n_in,
                              void* d_out, int out_size)
{
    (void)in_sizes; (void)n_in; (void)out_size;
    const float* start  = (const float*)d_in[0];
    // d_in[1] = end_state (unused)
    const float* te_w1  = (const float*)d_in[2];
    const float* te_b1  = (const float*)d_in[3];
    const float* te_w2  = (const float*)d_in[4];
    const float* te_b2  = (const float*)d_in[5];
    const float* w0     = (const float*)d_in[6];
    const float* b0     = (const float*)d_in[7];
    const float* w1     = (const float*)d_in[8];
    const float* b1     = (const float*)d_in[9];
    const float* w2     = (const float*)d_in[10];
    const float* b2     = (const float*)d_in[11];
    const float* w3     = (const float*)d_in[12];
    const float* b3     = (const float*)d_in[13];
    const float* w4     = (const float*)d_in[14];
    const float* b4     = (const float*)d_in[15];
    const float* wout   = (const float*)d_in[16];
    const float* bout   = (const float*)d_in[17];
    float* out = (float*)d_out;

    cudaFuncSetAttribute(bridge_kernel,
                         cudaFuncAttributeMaxDynamicSharedMemorySize, SMEM_BYTES);

    dim3 rg(GRID, 6);
    reorg_kernel<<<rg, 256>>>(w0, w1, w2, w3, w4, wout);
    init_kernel<<<NSTEP, TE>>>(start, te_w1, te_b1, te_w2, te_b2, out);
    bridge_kernel<<<GRID, BLOCK, SMEM_BYTES>>>(b0, b1, b2, b3, b4, bout, out);
}

// round 10
// speedup vs baseline: 1.5731x; 1.0598x over previous
#include <cuda_runtime.h>
#include <cuda_bf16.h>
#include <cstdint>

#define GENE   2000
#define TE     128
#define HID    2048
#define KIN    2128      // GENE + TE (time embedding lives in x tail)
#define NSTEP  256
#define GRID   128
#define BLOCK  512
#define NCOL   16        // output columns per CTA
#define DT     (1.0f/255.0f)
#define CHUNK  512
#define NBUF   5
#define LOOKAHEAD 4                         // chunks in flight; wait_group 3
#define BUF_BYTES (CHUNK*NCOL*2)            // 16 KB (bf16)
#define XS_FLOATS 2176
#define SMEM_BYTES (XS_FLOATS*4 + NBUF*BUF_BYTES)

// Permuted bf16 weights: per-CTA slice contiguous.
#define OFF0   0L
#define OFF1   (OFF0 + 128L*KIN*NCOL)
#define OFF2   (OFF1 + 128L*HID*NCOL)
#define OFF3   (OFF2 + 128L*HID*NCOL)
#define OFF4   (OFF3 + 128L*HID*NCOL)
#define OFFO   (OFF4 + 128L*HID*NCOL)
#define TOTALF (OFFO + 125L*HID*NCOL)       // ~25.2M bf16 = ~48 MB

// Persistent scratch (device globals: allocation is forbidden)
__device__ __nv_bfloat16 g_wrep[TOTALF];
__device__ float    g_x[2][2176];      // x ping-pong: [0,2000)=x, [2000,2128)=te(t)
__device__ float    g_h0[HID];
__device__ float    g_h1[HID];
__device__ float    g_te[NSTEP][TE];
__device__ unsigned g_count;           // flat barrier counter (red-based)

// ---------------------------------------------------------------------------
// Grid barrier: FLAT monotonic counter. Arrival = red.release (fire-and-
// forget, ~0.854 cyc/arrival at the LTS atomic ALU). The preceding
// __syncthreads + release cumulativity order all CTA stores; no extra fence.
// ---------------------------------------------------------------------------
__device__ __forceinline__ void grid_barrier(unsigned& nbar) {
    __syncthreads();
    ++nbar;
    if (threadIdx.x == 0) {
        asm volatile("red.release.gpu.add.u32 [%0], 1;" :: "l"(&g_count) : "memory");
        const unsigned target = nbar * GRID;
        unsigned cur;
        do {
            asm volatile("ld.acquire.gpu.u32 %0, [%1];" : "=r"(cur) : "l"(&g_count) : "memory");
        } while (cur < target);
    }
    __syncthreads();
}

// ---------------------------------------------------------------------------
// cp.async helpers
// ---------------------------------------------------------------------------
__device__ __forceinline__ void cp16(char* dst, const char* src) {
    unsigned a = (unsigned)__cvta_generic_to_shared(dst);
    asm volatile("cp.async.cg.shared.global [%0], [%1], 16;" :: "r"(a), "l"(src));
}

// One CHUNK-row slab (bf16, contiguous) -> smem buf. One commit, all threads.
__device__ __forceinline__ void prefetch_chunk(const char* __restrict__ slice,
        int K, int base, char* __restrict__ buf, int tid, bool active) {
    if (active) {
        const int lim = K * 2;            // 16B segments in whole slice
        const int s0  = base * 2;
        #pragma unroll
        for (int i = 0; i < (CHUNK*2)/BLOCK; ++i) {   // 2 segs/thread
            const int s = tid + i*BLOCK;
            if (s0 + s < lim)
                cp16(buf + s*16, slice + (long)(s0 + s)*16);
        }
    }
    asm volatile("cp.async.commit_group;");
}

// ---------------------------------------------------------------------------
// Layer. Pipeline identical to the 4536us best (chunks 0..3 in flight on
// entry; issues its remaining chunks then next layer's 0..3; one wait_group
// + one __syncthreads per chunk). Compute remapped: 8 cols per thread
// (jv=tid&1 selects 16B half-row, kw=tid>>1 in [0,256)), LDS.128 weight
// loads. Returns the column sum; valid for tid<16 (col j0+tid).
// ---------------------------------------------------------------------------
__device__ __forceinline__ float layer_core(
    const char* __restrict__ slice,  int K,  bool act,
    const char* __restrict__ slicen, int Kn, bool actn,
    const float* __restrict__ in,
    float* __restrict__ xs, char* __restrict__ bufs,
    int& is, int& rs, float (*red2)[2][8],
    int tid, unsigned& nbar)
{
    grid_barrier(nbar);

    // Stage input vector (fresh data from other SMs -> L2 path).
    const int K4 = K >> 2;
    for (int i = tid; i < K4; i += BLOCK)
        reinterpret_cast<float4*>(xs)[i] =
            __ldcg(reinterpret_cast<const float4*>(in) + i);

    const int kw = tid >> 1;          // row group, 0..255
    const int jv = tid & 1;           // which 16B half of the 32B row
    float acc[8];
    #pragma unroll
    for (int k = 0; k < 8; ++k) acc[k] = 0.f;

    const int nc = (K + CHUNK - 1) / CHUNK;
    for (int c = 0; c < nc; ++c) {
        asm volatile("cp.async.wait_group 3;");   // chunk c landed
        __syncthreads();                          // ..and chunk c-1 reads done

        // Refill the buffer freed by the sync just passed.
        if (c < nc - LOOKAHEAD)
            prefetch_chunk(slice,  K,  (c + LOOKAHEAD)*CHUNK,
                           bufs + is*BUF_BYTES, tid, act);
        else
            prefetch_chunk(slicen, Kn, (c - (nc - LOOKAHEAD))*CHUNK,
                           bufs + is*BUF_BYTES, tid, actn);
        if (++is == NBUF) is = 0;

        if (act) {
            const char* __restrict__ buf = bufs + rs*BUF_BYTES;
            const int base = c * CHUNK;
            const int rows = min(CHUNK, K - base);
            #pragma unroll
            for (int i = 0; i < CHUNK/(BLOCK/2); ++i) {   // 2 iters
                const int r = kw + i*(BLOCK/2);
                if (r < rows) {
                    const float xv = xs[base + r];
                    const uint4 wv = *reinterpret_cast<const uint4*>(buf + r*32 + jv*16);
                    const float2 f0 = __bfloat1622float2(*reinterpret_cast<const __nv_bfloat162*>(&wv.x));
                    const float2 f1 = __bfloat1622float2(*reinterpret_cast<const __nv_bfloat162*>(&wv.y));
                    const float2 f2 = __bfloat1622float2(*reinterpret_cast<const __nv_bfloat162*>(&wv.z));
                    const float2 f3 = __bfloat1622float2(*reinterpret_cast<const __nv_bfloat162*>(&wv.w));
                    acc[0] = fmaf(xv, f0.x, acc[0]);
                    acc[1] = fmaf(xv, f0.y, acc[1]);
                    acc[2] = fmaf(xv, f1.x, acc[2]);
                    acc[3] = fmaf(xv, f1.y, acc[3]);
                    acc[4] = fmaf(xv, f2.x, acc[4]);
                    acc[5] = fmaf(xv, f2.y, acc[5]);
                    acc[6] = fmaf(xv, f3.x, acc[6]);
                    acc[7] = fmaf(xv, f3.y, acc[7]);
                }
            }
        }
        if (++rs == NBUF) rs = 0;
    }

    // Reduce over the 16 kw groups within each warp (lane bits 1..4)
    #pragma unroll
    for (int m = 2; m <= 16; m <<= 1) {
        #pragma unroll
        for (int k = 0; k < 8; ++k)
            acc[k] += __shfl_xor_sync(0xffffffffu, acc[k], m);
    }
    const int warp = tid >> 5;
    const int lane = tid & 31;
    if (lane < 2) {
        #pragma unroll
        for (int k = 0; k < 8; ++k) red2[warp][lane][k] = acc[k];
    }
    __syncthreads();

    float r = 0.f;
    if (tid < NCOL) {                 // column j0 + tid
        const int cj = tid >> 3;      // which half (jv)
        const int ck = tid & 7;
        #pragma unroll
        for (int w = 0; w < 16; ++w)
            r += red2[w][cj][ck];
    }
    return r;   // valid for tid < 16
}

__device__ __forceinline__ void store_hidden(float r,
        const float* __restrict__ bias, float* __restrict__ out,
        int j0, int tid)
{
    if (tid < NCOL) {
        const int j = j0 + tid;
        out[j] = fmaxf(r + __ldg(bias + j), 0.f);
    }
}

// ---------------------------------------------------------------------------
// Weight reorg: permute + convert fp32 -> bf16, per-CTA-slice contiguous.
// ---------------------------------------------------------------------------
__global__ void reorg_kernel(
    const float* __restrict__ w0, const float* __restrict__ w1,
    const float* __restrict__ w2, const float* __restrict__ w3,
    const float* __restrict__ w4, const float* __restrict__ wout)
{
    const int b = blockIdx.x;   // slice
    const int l = blockIdx.y;   // layer
    const float* W; int K, O; long off;
    switch (l) {
        case 0: W = w0;   K = KIN; O = HID;  off = OFF0; break;
        case 1: W = w1;   K = HID; O = HID;  off = OFF1; break;
        case 2: W = w2;   K = HID; O = HID;  off = OFF2; break;
        case 3: W = w3;   K = HID; O = HID;  off = OFF3; break;
        case 4: W = w4;   K = HID; O = HID;  off = OFF4; break;
        default:W = wout; K = HID; O = GENE; off = OFFO; break;
    }
    const int j0 = b * NCOL;
    if (j0 >= O) return;
    __nv_bfloat16* dst = g_wrep + off + (long)b * K * NCOL;
    const int n4 = K * (NCOL/4);
    for (int e = threadIdx.x; e < n4; e += blockDim.x) {
        const int r  = e >> 2;
        const int c4 = (e & 3) * 4;
        const float4 w = *reinterpret_cast<const float4*>(W + (long)r * O + j0 + c4);
        uint2 p;
        __nv_bfloat162 p0 = __float22bfloat162_rn(make_float2(w.x, w.y));
        __nv_bfloat162 p1 = __float22bfloat162_rn(make_float2(w.z, w.w));
        p.x = *reinterpret_cast<unsigned*>(&p0);
        p.y = *reinterpret_cast<unsigned*>(&p1);
        *reinterpret_cast<uint2*>(dst + (long)e * 4) = p;
    }
}

// ---------------------------------------------------------------------------
// Init: reset barrier counter, seed x0 (+te(1) tail) + row 0, precompute te.
// ---------------------------------------------------------------------------
__global__ void init_kernel(
    const float* __restrict__ start,
    const float* __restrict__ te_w1, const float* __restrict__ te_b1,
    const float* __restrict__ te_w2, const float* __restrict__ te_b2,
    float* __restrict__ out)
{
    const int b   = blockIdx.x;     // 0..255
    const int tid = threadIdx.x;    // 128 threads
    if (b == 0) {
        if (tid == 0) g_count = 0u;
        for (int k = tid; k < GENE; k += TE) {
            const float v = start[k];
            g_x[0][k] = v;
            out[k]    = v;          // trajectory row 0
        }
    } else {
        const float t = (float)b * DT;
        __shared__ float h[TE];
        h[tid] = fmaxf(fmaf(t, te_w1[tid], te_b1[tid]), 0.f);
        __syncthreads();
        float acc = te_b2[tid];
        #pragma unroll 8
        for (int k = 0; k < TE; ++k)
            acc = fmaf(h[k], te_w2[k * TE + tid], acc);
        g_te[b][tid] = acc;
        if (b == 1) g_x[0][GENE + tid] = acc;   // te(1) tail for step 1
    }
}

// ---------------------------------------------------------------------------
// Persistent kernel: 255 Euler steps, 6 flat barriers/step, depth-5 cp.async
// streaming of contiguous bf16 weight slices, 4-chunk cross-layer lookahead.
// ---------------------------------------------------------------------------
__global__ void __launch_bounds__(BLOCK, 1) bridge_kernel(
    const float* __restrict__ b0, const float* __restrict__ b1,
    const float* __restrict__ b2, const float* __restrict__ b3,
    const float* __restrict__ b4, const float* __restrict__ bout,
    float* __restrict__ out)
{
    extern __shared__ float smem[];
    float* xs   = smem;                                 // 2176 floats
    char*  bufs = reinterpret_cast<char*>(smem + XS_FLOATS);
    __shared__ float red2[16][2][8];

    const int tid = threadIdx.x;
    const int b   = blockIdx.x;
    const int j0  = b * NCOL;
    const bool actO = (j0 < GENE);      // active in the output layer

    const char* s0 = reinterpret_cast<const char*>(g_wrep + OFF0 + (long)b * KIN * NCOL);
    const char* s1 = reinterpret_cast<const char*>(g_wrep + OFF1 + (long)b * HID * NCOL);
    const char* s2 = reinterpret_cast<const char*>(g_wrep + OFF2 + (long)b * HID * NCOL);
    const char* s3 = reinterpret_cast<const char*>(g_wrep + OFF3 + (long)b * HID * NCOL);
    const char* s4 = reinterpret_cast<const char*>(g_wrep + OFF4 + (long)b * HID * NCOL);
    const char* so = reinterpret_cast<const char*>(g_wrep + OFFO + (long)b * HID * NCOL);

    unsigned nbar = 0;
    int is = 0, rs = 0;

    // Prologue: chunks 0..3 of step-1 layer0
    #pragma unroll
    for (int c = 0; c < LOOKAHEAD; ++c)
        prefetch_chunk(s0, KIN, c*CHUNK, bufs + c*BUF_BYTES, tid, true);
    is = LOOKAHEAD;

    for (int t = 1; t < NSTEP; ++t) {
        const float* xprev = g_x[(t - 1) & 1];
        float*       xcur  = g_x[t & 1];
        float r;

        r = layer_core(s0, KIN, true,  s1, HID, true,  xprev,
                       xs, bufs, is, rs, red2, tid, nbar);
        store_hidden(r, b0, g_h0, j0, tid);

        r = layer_core(s1, HID, true,  s2, HID, true,  g_h0,
                       xs, bufs, is, rs, red2, tid, nbar);
        store_hidden(r, b1, g_h1, j0, tid);

        r = layer_core(s2, HID, true,  s3, HID, true,  g_h1,
                       xs, bufs, is, rs, red2, tid, nbar);
        store_hidden(r, b2, g_h0, j0, tid);

        r = layer_core(s3, HID, true,  s4, HID, true,  g_h0,
                       xs, bufs, is, rs, red2, tid, nbar);
        store_hidden(r, b3, g_h1, j0, tid);

        r = layer_core(s4, HID, true,  so, HID, actO,  g_h1,
                       xs, bufs, is, rs, red2, tid, nbar);
        store_hidden(r, b4, g_h0, j0, tid);

        // Final layer + Euler update + trajectory store
        r = layer_core(so, HID, actO,  s0, KIN, true,  g_h0,
                       xs, bufs, is, rs, red2, tid, nbar);
        if (tid < NCOL && actO) {
            const int j = j0 + tid;
            const float xn = fmaf(r + __ldg(bout + j), DT, __ldcg(xprev + j));
            xcur[j] = xn;
            __stcs(out + (size_t)t * GENE + j, xn);
        }
        // tail CTA installs te(t+1) into xcur tail for next step's layer0
        if (b == GRID - 1 && t + 1 < NSTEP && tid < TE)
            xcur[GENE + tid] = g_te[t + 1][tid];
    }
}

extern "C" void kernel_launch(void* const* d_in, const int* in_sizes, int n_in,
                              void* d_out, int out_size)
{
    (void)in_sizes; (void)n_in; (void)out_size;
    const float* start  = (const float*)d_in[0];
    // d_in[1] = end_state (unused)
    const float* te_w1  = (const float*)d_in[2];
    const float* te_b1  = (const float*)d_in[3];
    const float* te_w2  = (const float*)d_in[4];
    const float* te_b2  = (const float*)d_in[5];
    const float* w0     = (const float*)d_in[6];
    const float* b0     = (const float*)d_in[7];
    const float* w1     = (const float*)d_in[8];
    const float* b1     = (const float*)d_in[9];
    const float* w2     = (const float*)d_in[10];
    const float* b2     = (const float*)d_in[11];
    const float* w3     = (const float*)d_in[12];
    const float* b3     = (const float*)d_in[13];
    const float* w4     = (const float*)d_in[14];
    const float* b4     = (const float*)d_in[15];
    const float* wout   = (const float*)d_in[16];
    const float* bout   = (const float*)d_in[17];
    float* out = (float*)d_out;

    cudaFuncSetAttribute(bridge_kernel,
                         cudaFuncAttributeMaxDynamicSharedMemorySize, SMEM_BYTES);

    dim3 rg(GRID, 6);
    reorg_kernel<<<rg, 256>>>(w0, w1, w2, w3, w4, wout);
    init_kernel<<<NSTEP, TE>>>(start, te_w1, te_b1, te_w2, te_b2, out);
    bridge_kernel<<<GRID, BLOCK, SMEM_BYTES>>>(b0, b1, b2, b3, b4, bout, out);
}

// round 11
// speedup vs baseline: 1.6496x; 1.0486x over previous
#include <cuda_runtime.h>
#include <cuda_bf16.h>
#include <cstdint>

#define GENE   2000
#define TE     128
#define HID    2048
#define KIN    2128      // GENE + TE (time embedding lives in x tail)
#define NSTEP  256
#define GRID   128
#define BLOCK  512
#define NCOL   16        // output columns per CTA
#define DT     (1.0f/255.0f)
#define CHUNK  512
#define NBUF   5
#define LOOKAHEAD 4                         // chunks in flight; wait_group 3
#define BUF_BYTES (CHUNK*NCOL*2)            // 16 KB (bf16)
#define XS_FLOATS 2176
#define SLAB_BYTES (HID*NCOL*2)             // 64 KB resident slab per layer
#define SMEM_BYTES (XS_FLOATS*4 + NBUF*BUF_BYTES + 2*SLAB_BYTES)   // 216.5 KB

// Permuted bf16 weights: per-CTA slice contiguous.
#define OFF0   0L
#define OFF1   (OFF0 + 128L*KIN*NCOL)
#define OFF2   (OFF1 + 128L*HID*NCOL)
#define OFF3   (OFF2 + 128L*HID*NCOL)
#define OFF4   (OFF3 + 128L*HID*NCOL)
#define OFFO   (OFF4 + 128L*HID*NCOL)
#define TOTALF (OFFO + 125L*HID*NCOL)       // ~25.2M bf16 = ~48 MB

// Persistent scratch (device globals: allocation is forbidden)
__device__ __nv_bfloat16 g_wrep[TOTALF];
__device__ float    g_x[2][2176];      // x ping-pong: [0,2000)=x, [2000,2128)=te(t)
__device__ float    g_h0[HID];
__device__ float    g_h1[HID];
__device__ float    g_te[NSTEP][TE];
__device__ unsigned g_count;           // flat barrier counter (red-based)

// ---------------------------------------------------------------------------
// Grid barrier: FLAT monotonic counter (red.release arrival, acquire poll).
// ---------------------------------------------------------------------------
__device__ __forceinline__ void grid_barrier(unsigned& nbar) {
    __syncthreads();
    ++nbar;
    if (threadIdx.x == 0) {
        asm volatile("red.release.gpu.add.u32 [%0], 1;" :: "l"(&g_count) : "memory");
        const unsigned target = nbar * GRID;
        unsigned cur;
        do {
            asm volatile("ld.acquire.gpu.u32 %0, [%1];" : "=r"(cur) : "l"(&g_count) : "memory");
        } while (cur < target);
    }
    __syncthreads();
}

// ---------------------------------------------------------------------------
// cp.async helpers
// ---------------------------------------------------------------------------
__device__ __forceinline__ void cp16(char* dst, const char* src) {
    unsigned a = (unsigned)__cvta_generic_to_shared(dst);
    asm volatile("cp.async.cg.shared.global [%0], [%1], 16;" :: "r"(a), "l"(src));
}

// One CHUNK-row slab (bf16, contiguous) -> smem buf. One commit, all threads.
__device__ __forceinline__ void prefetch_chunk(const char* __restrict__ slice,
        int K, int base, char* __restrict__ buf, int tid, bool active) {
    if (active) {
        const int lim = K * 2;            // 16B segments in whole slice
        const int s0  = base * 2;
        #pragma unroll
        for (int i = 0; i < (CHUNK*2)/BLOCK; ++i) {   // 2 segs/thread
            const int s = tid + i*BLOCK;
            if (s0 + s < lim)
                cp16(buf + s*16, slice + (long)(s0 + s)*16);
        }
    }
    asm volatile("cp.async.commit_group;");
}

// 8-col MAC on one 32-byte weight row (jv selects the 16B half).
__device__ __forceinline__ void mac8(float* acc, const char* rowp, int jv, float xv) {
    const uint4 wv = *reinterpret_cast<const uint4*>(rowp + jv*16);
    const float2 f0 = __bfloat1622float2(*reinterpret_cast<const __nv_bfloat162*>(&wv.x));
    const float2 f1 = __bfloat1622float2(*reinterpret_cast<const __nv_bfloat162*>(&wv.y));
    const float2 f2 = __bfloat1622float2(*reinterpret_cast<const __nv_bfloat162*>(&wv.z));
    const float2 f3 = __bfloat1622float2(*reinterpret_cast<const __nv_bfloat162*>(&wv.w));
    acc[0] = fmaf(xv, f0.x, acc[0]);
    acc[1] = fmaf(xv, f0.y, acc[1]);
    acc[2] = fmaf(xv, f1.x, acc[2]);
    acc[3] = fmaf(xv, f1.y, acc[3]);
    acc[4] = fmaf(xv, f2.x, acc[4]);
    acc[5] = fmaf(xv, f2.y, acc[5]);
    acc[6] = fmaf(xv, f3.x, acc[6]);
    acc[7] = fmaf(xv, f3.y, acc[7]);
}

// Cross-thread reduction of 8-col accumulators. Returns column sum for
// tid<16 (col j0+tid).
__device__ __forceinline__ float reduce_tail(float* acc, float (*red2)[2][8], int tid) {
    #pragma unroll
    for (int m = 2; m <= 16; m <<= 1) {
        #pragma unroll
        for (int k = 0; k < 8; ++k)
            acc[k] += __shfl_xor_sync(0xffffffffu, acc[k], m);
    }
    const int warp = tid >> 5;
    const int lane = tid & 31;
    if (lane < 2) {
        #pragma unroll
        for (int k = 0; k < 8; ++k) red2[warp][lane][k] = acc[k];
    }
    __syncthreads();
    float r = 0.f;
    if (tid < NCOL) {
        const int cj = tid >> 3;
        const int ck = tid & 7;
        #pragma unroll
        for (int w = 0; w < 16; ++w)
            r += red2[w][cj][ck];
    }
    return r;
}

// ---------------------------------------------------------------------------
// Streamed layer (identical pipeline to the 4521us best): chunks 0..3 in
// flight on entry; issues its remaining chunks then next STREAMED layer's
// chunks 0..3. Result valid for tid<16.
// ---------------------------------------------------------------------------
__device__ __forceinline__ float stream_layer(
    const char* __restrict__ slice,  int K,  bool act,
    const char* __restrict__ slicen, int Kn, bool actn,
    const float* __restrict__ in,
    float* __restrict__ xs, char* __restrict__ bufs,
    int& is, int& rs, float (*red2)[2][8],
    int tid, unsigned& nbar)
{
    grid_barrier(nbar);

    const int K4 = K >> 2;
    for (int i = tid; i < K4; i += BLOCK)
        reinterpret_cast<float4*>(xs)[i] =
            __ldcg(reinterpret_cast<const float4*>(in) + i);

    const int kw = tid >> 1;
    const int jv = tid & 1;
    float acc[8];
    #pragma unroll
    for (int k = 0; k < 8; ++k) acc[k] = 0.f;

    const int nc = (K + CHUNK - 1) / CHUNK;
    for (int c = 0; c < nc; ++c) {
        asm volatile("cp.async.wait_group 3;");   // chunk c landed
        __syncthreads();                          // ..and chunk c-1 reads done

        if (c < nc - LOOKAHEAD)
            prefetch_chunk(slice,  K,  (c + LOOKAHEAD)*CHUNK,
                           bufs + is*BUF_BYTES, tid, act);
        else
            prefetch_chunk(slicen, Kn, (c - (nc - LOOKAHEAD))*CHUNK,
                           bufs + is*BUF_BYTES, tid, actn);
        if (++is == NBUF) is = 0;

        if (act) {
            const char* __restrict__ buf = bufs + rs*BUF_BYTES;
            const int base = c * CHUNK;
            const int rows = min(CHUNK, K - base);
            #pragma unroll
            for (int i = 0; i < CHUNK/(BLOCK/2); ++i) {   // 2 iters
                const int r = kw + i*(BLOCK/2);
                if (r < rows)
                    mac8(acc, buf + r*32, jv, xs[base + r]);
            }
        }
        if (++rs == NBUF) rs = 0;
    }
    return reduce_tail(acc, red2, tid);
}

// ---------------------------------------------------------------------------
// Resident layer: weights live permanently in SMEM. No chunk machinery —
// barrier, stage xs, one sync, straight-line 64 FMAs/thread, reduce.
// Row-visit order per thread identical to the streamed version (bit-exact).
// ---------------------------------------------------------------------------
__device__ __forceinline__ float resident_layer(
    const char* __restrict__ wres,
    const float* __restrict__ in,
    float* __restrict__ xs, float (*red2)[2][8],
    int tid, unsigned& nbar)
{
    grid_barrier(nbar);

    for (int i = tid; i < HID/4; i += BLOCK)
        reinterpret_cast<float4*>(xs)[i] =
            __ldcg(reinterpret_cast<const float4*>(in) + i);
    __syncthreads();

    const int kw = tid >> 1;
    const int jv = tid & 1;
    float acc[8];
    #pragma unroll
    for (int k = 0; k < 8; ++k) acc[k] = 0.f;

    #pragma unroll
    for (int i = 0; i < HID/(BLOCK/2); ++i) {     // 8 iters
        const int r = kw + i*(BLOCK/2);
        mac8(acc, wres + r*32, jv, xs[r]);
    }
    return reduce_tail(acc, red2, tid);
}

__device__ __forceinline__ void store_hidden(float r,
        const float* __restrict__ bias, float* __restrict__ out,
        int j0, int tid)
{
    if (tid < NCOL) {
        const int j = j0 + tid;
        out[j] = fmaxf(r + __ldg(bias + j), 0.f);
    }
}

// ---------------------------------------------------------------------------
// Weight reorg: permute + convert fp32 -> bf16, per-CTA-slice contiguous.
// ---------------------------------------------------------------------------
__global__ void reorg_kernel(
    const float* __restrict__ w0, const float* __restrict__ w1,
    const float* __restrict__ w2, const float* __restrict__ w3,
    const float* __restrict__ w4, const float* __restrict__ wout)
{
    const int b = blockIdx.x;   // slice
    const int l = blockIdx.y;   // layer
    const float* W; int K, O; long off;
    switch (l) {
        case 0: W = w0;   K = KIN; O = HID;  off = OFF0; break;
        case 1: W = w1;   K = HID; O = HID;  off = OFF1; break;
        case 2: W = w2;   K = HID; O = HID;  off = OFF2; break;
        case 3: W = w3;   K = HID; O = HID;  off = OFF3; break;
        case 4: W = w4;   K = HID; O = HID;  off = OFF4; break;
        default:W = wout; K = HID; O = GENE; off = OFFO; break;
    }
    const int j0 = b * NCOL;
    if (j0 >= O) return;
    __nv_bfloat16* dst = g_wrep + off + (long)b * K * NCOL;
    const int n4 = K * (NCOL/4);
    for (int e = threadIdx.x; e < n4; e += blockDim.x) {
        const int r  = e >> 2;
        const int c4 = (e & 3) * 4;
        const float4 w = *reinterpret_cast<const float4*>(W + (long)r * O + j0 + c4);
        uint2 p;
        __nv_bfloat162 p0 = __float22bfloat162_rn(make_float2(w.x, w.y));
        __nv_bfloat162 p1 = __float22bfloat162_rn(make_float2(w.z, w.w));
        p.x = *reinterpret_cast<unsigned*>(&p0);
        p.y = *reinterpret_cast<unsigned*>(&p1);
        *reinterpret_cast<uint2*>(dst + (long)e * 4) = p;
    }
}

// ---------------------------------------------------------------------------
// Init: reset barrier counter, seed x0 (+te(1) tail) + row 0, precompute te.
// ---------------------------------------------------------------------------
__global__ void init_kernel(
    const float* __restrict__ start,
    const float* __restrict__ te_w1, const float* __restrict__ te_b1,
    const float* __restrict__ te_w2, const float* __restrict__ te_b2,
    float* __restrict__ out)
{
    const int b   = blockIdx.x;     // 0..255
    const int tid = threadIdx.x;    // 128 threads
    if (b == 0) {
        if (tid == 0) g_count = 0u;
        for (int k = tid; k < GENE; k += TE) {
            const float v = start[k];
            g_x[0][k] = v;
            out[k]    = v;          // trajectory row 0
        }
    } else {
        const float t = (float)b * DT;
        __shared__ float h[TE];
        h[tid] = fmaxf(fmaf(t, te_w1[tid], te_b1[tid]), 0.f);
        __syncthreads();
        float acc = te_b2[tid];
        #pragma unroll 8
        for (int k = 0; k < TE; ++k)
            acc = fmaf(h[k], te_w2[k * TE + tid], acc);
        g_te[b][tid] = acc;
        if (b == 1) g_x[0][GENE + tid] = acc;   // te(1) tail for step 1
    }
}

// ---------------------------------------------------------------------------
// Persistent kernel: 255 Euler steps, 6 flat barriers/step. Layers 1-2 run
// from SMEM-resident weight slabs (loaded once); layers 0,3,4,out stream via
// the depth-5 cp.async pipeline with 4-chunk cross-layer lookahead.
// ---------------------------------------------------------------------------
__global__ void __launch_bounds__(BLOCK, 1) bridge_kernel(
    const float* __restrict__ b0, const float* __restrict__ b1,
    const float* __restrict__ b2, const float* __restrict__ b3,
    const float* __restrict__ b4, const float* __restrict__ bout,
    float* __restrict__ out)
{
    extern __shared__ float smem[];
    float* xs   = smem;                                 // 2176 floats
    char*  bufs = reinterpret_cast<char*>(smem + XS_FLOATS);
    char*  rw1  = bufs + NBUF*BUF_BYTES;                // resident w1 slab
    char*  rw2  = rw1 + SLAB_BYTES;                     // resident w2 slab
    __shared__ float red2[16][2][8];

    const int tid = threadIdx.x;
    const int b   = blockIdx.x;
    const int j0  = b * NCOL;
    const bool actO = (j0 < GENE);      // active in the output layer

    const char* s0 = reinterpret_cast<const char*>(g_wrep + OFF0 + (long)b * KIN * NCOL);
    const char* s1 = reinterpret_cast<const char*>(g_wrep + OFF1 + (long)b * HID * NCOL);
    const char* s2 = reinterpret_cast<const char*>(g_wrep + OFF2 + (long)b * HID * NCOL);
    const char* s3 = reinterpret_cast<const char*>(g_wrep + OFF3 + (long)b * HID * NCOL);
    const char* s4 = reinterpret_cast<const char*>(g_wrep + OFF4 + (long)b * HID * NCOL);
    const char* so = reinterpret_cast<const char*>(g_wrep + OFFO + (long)b * HID * NCOL);

    unsigned nbar = 0;
    int is = 0, rs = 0;

    // Prologue: resident slabs (one cp.async group, drains at first wait),
    // then chunks 0..3 of step-1 layer0.
    for (int i = tid; i < SLAB_BYTES/16; i += BLOCK) cp16(rw1 + i*16, s1 + (long)i*16);
    for (int i = tid; i < SLAB_BYTES/16; i += BLOCK) cp16(rw2 + i*16, s2 + (long)i*16);
    asm volatile("cp.async.commit_group;");
    #pragma unroll
    for (int c = 0; c < LOOKAHEAD; ++c)
        prefetch_chunk(s0, KIN, c*CHUNK, bufs + c*BUF_BYTES, tid, true);
    is = LOOKAHEAD;

    for (int t = 1; t < NSTEP; ++t) {
        const float* xprev = g_x[(t - 1) & 1];
        float*       xcur  = g_x[t & 1];
        float r;

        r = stream_layer(s0, KIN, true,  s3, HID, true,  xprev,
                         xs, bufs, is, rs, red2, tid, nbar);
        store_hidden(r, b0, g_h0, j0, tid);

        r = resident_layer(rw1, g_h0, xs, red2, tid, nbar);
        store_hidden(r, b1, g_h1, j0, tid);

        r = resident_layer(rw2, g_h1, xs, red2, tid, nbar);
        store_hidden(r, b2, g_h0, j0, tid);

        r = stream_layer(s3, HID, true,  s4, HID, true,  g_h0,
                         xs, bufs, is, rs, red2, tid, nbar);
        store_hidden(r, b3, g_h1, j0, tid);

        r = stream_layer(s4, HID, true,  so, HID, actO,  g_h1,
                         xs, bufs, is, rs, red2, tid, nbar);
        store_hidden(r, b4, g_h0, j0, tid);

        // Final layer + Euler update + trajectory store
        r = stream_layer(so, HID, actO,  s0, KIN, true,  g_h0,
                         xs, bufs, is, rs, red2, tid, nbar);
        if (tid < NCOL && actO) {
            const int j = j0 + tid;
            const float xn = fmaf(r + __ldg(bout + j), DT, __ldcg(xprev + j));
            xcur[j] = xn;
            __stcs(out + (size_t)t * GENE + j, xn);
        }
        // tail CTA installs te(t+1) into xcur tail for next step's layer0
        if (b == GRID - 1 && t + 1 < NSTEP && tid < TE)
            xcur[GENE + tid] = g_te[t + 1][tid];
    }
}

extern "C" void kernel_launch(void* const* d_in, const int* in_sizes, int n_in,
                              void* d_out, int out_size)
{
    (void)in_sizes; (void)n_in; (void)out_size;
    const float* start  = (const float*)d_in[0];
    // d_in[1] = end_state (unused)
    const float* te_w1  = (const float*)d_in[2];
    const float* te_b1  = (const float*)d_in[3];
    const float* te_w2  = (const float*)d_in[4];
    const float* te_b2  = (const float*)d_in[5];
    const float* w0     = (const float*)d_in[6];
    const float* b0     = (const float*)d_in[7];
    const float* w1     = (const float*)d_in[8];
    const float* b1     = (const float*)d_in[9];
    const float* w2     = (const float*)d_in[10];
    const float* b2     = (const float*)d_in[11];
    const float* w3     = (const float*)d_in[12];
    const float* b3     = (const float*)d_in[13];
    const float* w4     = (const float*)d_in[14];
    const float* b4     = (const float*)d_in[15];
    const float* wout   = (const float*)d_in[16];
    const float* bout   = (const float*)d_in[17];
    float* out = (float*)d_out;

    cudaFuncSetAttribute(bridge_kernel,
                         cudaFuncAttributeMaxDynamicSharedMemorySize, SMEM_BYTES);

    dim3 rg(GRID, 6);
    reorg_kernel<<<rg, 256>>>(w0, w1, w2, w3, w4, wout);
    init_kernel<<<NSTEP, TE>>>(start, te_w1, te_b1, te_w2, te_b2, out);
    bridge_kernel<<<GRID, BLOCK, SMEM_BYTES>>>(b0, b1, b2, b3, b4, bout, out);
}